// round 1
// baseline (speedup 1.0000x reference)
#include <cuda_runtime.h>

// Problem constants
#define BATCH   8
#define SEQL    1024
#define DMODEL  512
#define DINNER  1024
#define DSTATE  16
#define DCONV   4
#define DTRANK  32
#define E2      2048            // 2*DINNER
#define MROWS   8192            // BATCH*SEQL

// ---------------------------------------------------------------------------
// Scratch (static __device__ arrays; no allocation in kernel_launch)
// ---------------------------------------------------------------------------
__device__ __align__(16) float g_xn  [MROWS * DMODEL];   // layernorm out
__device__ __align__(16) float g_xz  [MROWS * E2];       // in_proj out (u_raw | z)
__device__ __align__(16) float g_u   [MROWS * DINNER];   // conv+silu out
__device__ __align__(16) float g_dtr [MROWS * DTRANK];   // x_proj dt-rank part (packed)
__device__ __align__(16) float g_bc  [MROWS * 48];       // x_proj B|C part (packed 16+16 -> 48? see below)
__device__ __align__(16) float g_dt  [MROWS * DINNER];   // softplus(dt_proj) out
__device__ __align__(16) float g_y   [MROWS * DINNER];   // scan out (pre out_proj)

// g_bc layout: row m -> [B[0..16), C[0..16)] packed as 48? We only need 32 floats,
// but keep stride 48 unused tail for 16B alignment simplicity? Actually 32 works:
// stride 48 chosen so row offset stays multiple of 16B either way; we use stride 48
// with elements [0..16)=B, [16..32)=C, [32..48) unused.

// ---------------------------------------------------------------------------
// LayerNorm: one block (128 threads) per row of 512
// ---------------------------------------------------------------------------
__global__ void layernorm_kernel(const float* __restrict__ x,
                                 const float* __restrict__ w,
                                 const float* __restrict__ b,
                                 float* __restrict__ out)
{
    const int row = blockIdx.x;
    const int tid = threadIdx.x;                 // 128 threads, 4 elems each
    __shared__ float red[8];

    const float4 v = *(const float4*)(x + (size_t)row * DMODEL + tid * 4);

    float s = v.x + v.y + v.z + v.w;
    #pragma unroll
    for (int o = 16; o > 0; o >>= 1) s += __shfl_xor_sync(0xffffffffu, s, o);
    if ((tid & 31) == 0) red[tid >> 5] = s;
    __syncthreads();
    const float mu = (red[0] + red[1] + red[2] + red[3]) * (1.0f / DMODEL);

    const float dx = v.x - mu, dy = v.y - mu, dz = v.z - mu, dw = v.w - mu;
    float q = dx * dx + dy * dy + dz * dz + dw * dw;
    #pragma unroll
    for (int o = 16; o > 0; o >>= 1) q += __shfl_xor_sync(0xffffffffu, q, o);
    if ((tid & 31) == 0) red[4 + (tid >> 5)] = q;
    __syncthreads();
    const float var = (red[4] + red[5] + red[6] + red[7]) * (1.0f / DMODEL);
    const float rs = rsqrtf(var + 1e-5f);

    const float4 wv = *(const float4*)(w + tid * 4);
    const float4 bv = *(const float4*)(b + tid * 4);
    float4 o4;
    o4.x = dx * rs * wv.x + bv.x;
    o4.y = dy * rs * wv.y + bv.y;
    o4.z = dz * rs * wv.z + bv.z;
    o4.w = dw * rs * wv.w + bv.w;
    *(float4*)(out + (size_t)row * DMODEL + tid * 4) = o4;
}

// ---------------------------------------------------------------------------
// SGEMM (NT): C[m,n] = sum_k A[m,k] * W[n,k]
// 128x128 block tile, BK=8, 256 threads, 8x8 microtile.
// EPI: 0 = plain store
//      1 = softplus(acc + bias[n])
//      2 = acc + res[m*N+n]      (residual add)
//      3 = split store: n<32 -> C[m*32+n], 32<=n<80 -> C2[m*48 + (n-32)]
// Requires: M % 128 == 0, K % 8 == 0. N may be arbitrary (guarded).
// ---------------------------------------------------------------------------
template <int EPI>
__global__ void sgemm_nt(const float* __restrict__ A,
                         const float* __restrict__ W,
                         float* __restrict__ C,
                         int M, int N, int K,
                         const float* __restrict__ bias,
                         const float* __restrict__ res,
                         float* __restrict__ C2)
{
    __shared__ float As[8][128];
    __shared__ float Bs[8][128];

    const int tid = threadIdx.x;           // 0..255
    const int m0  = blockIdx.y * 128;
    const int n0  = blockIdx.x * 128;
    const int tx  = tid & 15;              // 0..15
    const int ty  = tid >> 4;              // 0..15

    const int lrow = tid >> 1;             // 0..127
    const int lkg  = (tid & 1) * 4;        // 0 or 4

    float acc[8][8];
    #pragma unroll
    for (int i = 0; i < 8; i++)
        #pragma unroll
        for (int j = 0; j < 8; j++) acc[i][j] = 0.0f;

    for (int k0 = 0; k0 < K; k0 += 8) {
        // Load A tile (coalesced along K), transpose into As[k][m]
        {
            const float4 v = *(const float4*)(A + (size_t)(m0 + lrow) * K + k0 + lkg);
            As[lkg + 0][lrow] = v.x;
            As[lkg + 1][lrow] = v.y;
            As[lkg + 2][lrow] = v.z;
            As[lkg + 3][lrow] = v.w;
        }
        // Load W tile (coalesced along K), transpose into Bs[k][n]
        {
            const int n = n0 + lrow;
            float4 v = make_float4(0.f, 0.f, 0.f, 0.f);
            if (n < N) v = *(const float4*)(W + (size_t)n * K + k0 + lkg);
            Bs[lkg + 0][lrow] = v.x;
            Bs[lkg + 1][lrow] = v.y;
            Bs[lkg + 2][lrow] = v.z;
            Bs[lkg + 3][lrow] = v.w;
        }
        __syncthreads();

        #pragma unroll
        for (int k = 0; k < 8; k++) {
            float a[8], bb[8];
            *(float4*)&a[0]  = *(const float4*)&As[k][ty * 8];
            *(float4*)&a[4]  = *(const float4*)&As[k][ty * 8 + 4];
            *(float4*)&bb[0] = *(const float4*)&Bs[k][tx * 8];
            *(float4*)&bb[4] = *(const float4*)&Bs[k][tx * 8 + 4];
            #pragma unroll
            for (int i = 0; i < 8; i++)
                #pragma unroll
                for (int j = 0; j < 8; j++)
                    acc[i][j] += a[i] * bb[j];
        }
        __syncthreads();
    }

    // Epilogue
    #pragma unroll
    for (int i = 0; i < 8; i++) {
        const int m = m0 + ty * 8 + i;
        #pragma unroll
        for (int j = 0; j < 8; j++) {
            const int n = n0 + tx * 8 + j;
            if (n >= N) continue;
            float v = acc[i][j];
            if (EPI == 0) {
                C[(size_t)m * N + n] = v;
            } else if (EPI == 1) {
                v += bias[n];
                // softplus
                v = (v > 20.0f) ? v : log1pf(expf(v));
                C[(size_t)m * N + n] = v;
            } else if (EPI == 2) {
                C[(size_t)m * N + n] = v + res[(size_t)m * N + n];
            } else { // EPI == 3 : split x_dbl
                if (n < DTRANK) C[(size_t)m * DTRANK + n] = v;
                else            C2[(size_t)m * 48 + (n - DTRANK)] = v;
            }
        }
    }
}

// ---------------------------------------------------------------------------
// Causal depthwise conv (width 4) + bias + SiLU.
// u_raw lives in g_xz columns [0, DINNER). Output g_u[m, d].
// ---------------------------------------------------------------------------
__global__ void conv_silu_kernel(const float* __restrict__ xz,
                                 const float* __restrict__ conv_w,
                                 const float* __restrict__ conv_b,
                                 float* __restrict__ u)
{
    const int idx = blockIdx.x * blockDim.x + threadIdx.x;  // 0 .. MROWS*DINNER
    if (idx >= MROWS * DINNER) return;
    const int d = idx & (DINNER - 1);
    const int m = idx >> 10;            // /DINNER
    const int l = m & (SEQL - 1);
    const int b = m >> 10;              // /SEQL

    const float w0 = conv_w[d * 4 + 0];
    const float w1 = conv_w[d * 4 + 1];
    const float w2 = conv_w[d * 4 + 2];
    const float w3 = conv_w[d * 4 + 3];

    float a = conv_b[d];
    const size_t base = ((size_t)(b << 10)) * E2 + d;   // row (b*L + 0)
    // out[l] = w0*u[l-3] + w1*u[l-2] + w2*u[l-1] + w3*u[l]
    if (l >= 3) a += w0 * xz[base + (size_t)(l - 3) * E2];
    if (l >= 2) a += w1 * xz[base + (size_t)(l - 2) * E2];
    if (l >= 1) a += w2 * xz[base + (size_t)(l - 1) * E2];
    a += w3 * xz[base + (size_t)l * E2];

    // silu
    const float s = 1.0f / (1.0f + __expf(-a));
    u[idx] = a * s;
}

// ---------------------------------------------------------------------------
// Selective scan. 4 states per thread -> 32768 threads (1024 warps).
// Lanes {4c, 4c+1, 4c+2, 4c+3} cooperate on one (b, d) channel.
// Fused: y = (scan + D*u) * silu(z).
// ---------------------------------------------------------------------------
__global__ void scan_kernel(const float* __restrict__ bc,      // [M, 48] B|C
                            const float* __restrict__ dt_arr,  // [M, DINNER]
                            const float* __restrict__ u_arr,   // [M, DINNER]
                            const float* __restrict__ xz,      // [M, E2] (z at +DINNER)
                            const float* __restrict__ A_log,   // [DINNER, 16]
                            const float* __restrict__ D_param, // [DINNER]
                            float* __restrict__ y_out)         // [M, DINNER]
{
    const int g  = blockIdx.x * blockDim.x + threadIdx.x;  // 0..32767
    const int sg = g & 3;                                  // state group (4 states)
    const int ch = g >> 2;                                 // 0..8191
    const int d  = ch & (DINNER - 1);
    const int b  = ch >> 10;

    float A[4];
    #pragma unroll
    for (int i = 0; i < 4; i++)
        A[i] = -__expf(A_log[d * DSTATE + sg * 4 + i]);
    const float Dp = D_param[d];

    float h0 = 0.f, h1 = 0.f, h2 = 0.f, h3 = 0.f;
    const int rowbase = b * SEQL;

    for (int l = 0; l < SEQL; l++) {
        const int m = rowbase + l;
        const float dt = dt_arr[(size_t)m * DINNER + d];
        const float ut = u_arr[(size_t)m * DINNER + d];
        const float4 Bv = *(const float4*)(bc + (size_t)m * 48 + sg * 4);
        const float4 Cv = *(const float4*)(bc + (size_t)m * 48 + 16 + sg * 4);
        const float dtu = dt * ut;

        h0 = __expf(dt * A[0]) * h0 + dtu * Bv.x;
        h1 = __expf(dt * A[1]) * h1 + dtu * Bv.y;
        h2 = __expf(dt * A[2]) * h2 + dtu * Bv.z;
        h3 = __expf(dt * A[3]) * h3 + dtu * Bv.w;

        float acc = h0 * Cv.x + h1 * Cv.y + h2 * Cv.z + h3 * Cv.w;
        acc += __shfl_xor_sync(0xffffffffu, acc, 1);
        acc += __shfl_xor_sync(0xffffffffu, acc, 2);

        if (sg == 0) {
            const float zt = xz[(size_t)m * E2 + DINNER + d];
            const float sig = 1.0f / (1.0f + __expf(-zt));
            y_out[(size_t)m * DINNER + d] = (acc + Dp * ut) * (zt * sig);
        }
    }
}

// ---------------------------------------------------------------------------
// Launch
// ---------------------------------------------------------------------------
extern "C" void kernel_launch(void* const* d_in, const int* in_sizes, int n_in,
                              void* d_out, int out_size)
{
    const float* x         = (const float*)d_in[0];
    const float* norm_w    = (const float*)d_in[1];
    const float* norm_b    = (const float*)d_in[2];
    const float* in_proj_w = (const float*)d_in[3];
    const float* conv_w    = (const float*)d_in[4];
    const float* conv_b    = (const float*)d_in[5];
    const float* x_proj_w  = (const float*)d_in[6];
    const float* dt_proj_w = (const float*)d_in[7];
    const float* dt_proj_b = (const float*)d_in[8];
    const float* A_log     = (const float*)d_in[9];
    const float* D_param   = (const float*)d_in[10];
    const float* out_proj_w= (const float*)d_in[11];
    float* out = (float*)d_out;

    static float *p_xn = nullptr, *p_xz, *p_u, *p_dtr, *p_bc, *p_dt, *p_y;
    if (!p_xn) {
        cudaGetSymbolAddress((void**)&p_xn,  g_xn);
        cudaGetSymbolAddress((void**)&p_xz,  g_xz);
        cudaGetSymbolAddress((void**)&p_u,   g_u);
        cudaGetSymbolAddress((void**)&p_dtr, g_dtr);
        cudaGetSymbolAddress((void**)&p_bc,  g_bc);
        cudaGetSymbolAddress((void**)&p_dt,  g_dt);
        cudaGetSymbolAddress((void**)&p_y,   g_y);
    }

    // 1. LayerNorm
    layernorm_kernel<<<MROWS, 128>>>(x, norm_w, norm_b, p_xn);

    // 2. in_proj: xz[8192, 2048] = xn @ in_proj_w^T
    sgemm_nt<0><<<dim3(E2 / 128, MROWS / 128), 256>>>(
        p_xn, in_proj_w, p_xz, MROWS, E2, DMODEL, nullptr, nullptr, nullptr);

    // 3. causal depthwise conv + SiLU -> u
    conv_silu_kernel<<<(MROWS * DINNER) / 256, 256>>>(p_xz, conv_w, conv_b, p_u);

    // 4. x_proj: x_dbl[8192, 80] = u @ x_proj_w^T, split into dtr[.,32] and bc[.,48]
    sgemm_nt<3><<<dim3(1, MROWS / 128), 256>>>(
        p_u, x_proj_w, p_dtr, MROWS, 80, DINNER, nullptr, nullptr, p_bc);

    // 5. dt_proj + bias + softplus: dt[8192, 1024]
    sgemm_nt<1><<<dim3(DINNER / 128, MROWS / 128), 256>>>(
        p_dtr, dt_proj_w, p_dt, MROWS, DINNER, DTRANK, dt_proj_b, nullptr, nullptr);

    // 6. selective scan + D*u + silu(z) gate -> y
    scan_kernel<<<(MROWS * 4) / 256, 256>>>(p_bc, p_dt, p_u, p_xz, A_log, D_param, p_y);

    // 7. out_proj + residual: out[8192, 512] = y @ out_proj_w^T + x
    sgemm_nt<2><<<dim3(DMODEL / 128, MROWS / 128), 256>>>(
        p_y, out_proj_w, out, MROWS, DMODEL, DINNER, nullptr, x, nullptr);
}

// round 2
// speedup vs baseline: 1.4670x; 1.4670x over previous
#include <cuda_runtime.h>

// Problem constants
#define BATCH   8
#define SEQL    1024
#define DMODEL  512
#define DINNER  1024
#define DSTATE  16
#define DCONV   4
#define DTRANK  32
#define E2      2048            // 2*DINNER
#define MROWS   8192            // BATCH*SEQL

// ---------------------------------------------------------------------------
// Scratch (static __device__ arrays; no allocation in kernel_launch)
// ---------------------------------------------------------------------------
__device__ __align__(16) float g_xn  [MROWS * DMODEL];   // layernorm out
__device__ __align__(16) float g_xz  [MROWS * E2];       // in_proj out (u_raw | z)
__device__ __align__(16) float g_u   [MROWS * DINNER];   // conv+silu out
__device__ __align__(16) float g_dtr [MROWS * DTRANK];   // x_proj dt-rank part
__device__ __align__(16) float g_bc  [MROWS * 48];       // x_proj B|C part (stride 48)
__device__ __align__(16) float g_dt  [MROWS * DINNER];   // softplus(dt_proj) out
__device__ __align__(16) float g_y   [MROWS * DINNER];   // scan out (pre out_proj)

// ---------------------------------------------------------------------------
// Helpers
// ---------------------------------------------------------------------------
__device__ __forceinline__ unsigned f2tf(float x) {
    unsigned r;
    asm("cvt.rna.tf32.f32 %0, %1;" : "=r"(r) : "f"(x));
    return r;
}

__device__ __forceinline__ void mma_m16n8k8(float* c, const unsigned* a, const unsigned* b) {
    asm volatile(
        "mma.sync.aligned.m16n8k8.row.col.f32.tf32.tf32.f32 "
        "{%0,%1,%2,%3}, {%4,%5,%6,%7}, {%8,%9}, {%0,%1,%2,%3};\n"
        : "+f"(c[0]), "+f"(c[1]), "+f"(c[2]), "+f"(c[3])
        : "r"(a[0]), "r"(a[1]), "r"(a[2]), "r"(a[3]), "r"(b[0]), "r"(b[1]));
}

// ---------------------------------------------------------------------------
// LayerNorm: one block (128 threads) per row of 512
// ---------------------------------------------------------------------------
__global__ void layernorm_kernel(const float* __restrict__ x,
                                 const float* __restrict__ w,
                                 const float* __restrict__ b,
                                 float* __restrict__ out)
{
    const int row = blockIdx.x;
    const int tid = threadIdx.x;
    __shared__ float red[8];

    const float4 v = *(const float4*)(x + (size_t)row * DMODEL + tid * 4);

    float s = v.x + v.y + v.z + v.w;
    #pragma unroll
    for (int o = 16; o > 0; o >>= 1) s += __shfl_xor_sync(0xffffffffu, s, o);
    if ((tid & 31) == 0) red[tid >> 5] = s;
    __syncthreads();
    const float mu = (red[0] + red[1] + red[2] + red[3]) * (1.0f / DMODEL);

    const float dx = v.x - mu, dy = v.y - mu, dz = v.z - mu, dw = v.w - mu;
    float q = dx * dx + dy * dy + dz * dz + dw * dw;
    #pragma unroll
    for (int o = 16; o > 0; o >>= 1) q += __shfl_xor_sync(0xffffffffu, q, o);
    if ((tid & 31) == 0) red[4 + (tid >> 5)] = q;
    __syncthreads();
    const float var = (red[4] + red[5] + red[6] + red[7]) * (1.0f / DMODEL);
    const float rs = rsqrtf(var + 1e-5f);

    const float4 wv = *(const float4*)(w + tid * 4);
    const float4 bv = *(const float4*)(b + tid * 4);
    float4 o4;
    o4.x = dx * rs * wv.x + bv.x;
    o4.y = dy * rs * wv.y + bv.y;
    o4.z = dz * rs * wv.z + bv.z;
    o4.w = dw * rs * wv.w + bv.w;
    *(float4*)(out + (size_t)row * DMODEL + tid * 4) = o4;
}

// ---------------------------------------------------------------------------
// TF32 tensor-core GEMM (NT): C[m,n] = sum_k A[m,k] * W[n,k]
// 128x128 tile, BK=16, 256 threads = 8 warps (4 in M x 2 in N), 32x64 warp tile.
// tf32 conversion at SMEM store. Stride-20 padding => conflict-free frag LDS.
// EPI: 0 plain | 1 softplus(acc+bias[n]) | 2 acc+res | 3 split (dtr / bc)
// Requires M%128==0, K%16==0. N guarded.
// ---------------------------------------------------------------------------
template <int EPI>
__global__ __launch_bounds__(256, 2)
void mma_gemm(const float* __restrict__ A,
              const float* __restrict__ W,
              float* __restrict__ C,
              int M, int N, int K,
              const float* __restrict__ bias,
              const float* __restrict__ res,
              float* __restrict__ C2)
{
    __shared__ unsigned As[2][128][20];
    __shared__ unsigned Bs[2][128][20];

    const int tid  = threadIdx.x;
    const int m0   = blockIdx.y * 128;
    const int n0   = blockIdx.x * 128;
    const int warp = tid >> 5;
    const int lane = tid & 31;
    const int wm   = warp & 3;        // 0..3  (M)
    const int wn   = warp >> 2;       // 0..1  (N)
    const int g    = lane >> 2;       // 0..7
    const int tg   = lane & 3;        // 0..3

    const int lr = tid >> 2;          // 0..63 (tile-load row)
    const int lc = (tid & 3) * 4;     // 0,4,8,12 (tile-load col)

    float acc[2][8][4];
    #pragma unroll
    for (int mi = 0; mi < 2; mi++)
        #pragma unroll
        for (int ni = 0; ni < 8; ni++)
            #pragma unroll
            for (int j = 0; j < 4; j++) acc[mi][ni][j] = 0.0f;

    float4 sa0, sa1, sb0, sb1;
    const float4 z4 = make_float4(0.f, 0.f, 0.f, 0.f);

    // --- prologue: load tile 0 ---
    {
        const int k0 = 0;
        sa0 = *(const float4*)(A + (size_t)(m0 + lr) * K + k0 + lc);
        sa1 = *(const float4*)(A + (size_t)(m0 + lr + 64) * K + k0 + lc);
        const int n1 = n0 + lr, n2 = n0 + lr + 64;
        sb0 = (n1 < N) ? *(const float4*)(W + (size_t)n1 * K + k0 + lc) : z4;
        sb1 = (n2 < N) ? *(const float4*)(W + (size_t)n2 * K + k0 + lc) : z4;
        As[0][lr][lc + 0] = f2tf(sa0.x); As[0][lr][lc + 1] = f2tf(sa0.y);
        As[0][lr][lc + 2] = f2tf(sa0.z); As[0][lr][lc + 3] = f2tf(sa0.w);
        As[0][lr + 64][lc + 0] = f2tf(sa1.x); As[0][lr + 64][lc + 1] = f2tf(sa1.y);
        As[0][lr + 64][lc + 2] = f2tf(sa1.z); As[0][lr + 64][lc + 3] = f2tf(sa1.w);
        Bs[0][lr][lc + 0] = f2tf(sb0.x); Bs[0][lr][lc + 1] = f2tf(sb0.y);
        Bs[0][lr][lc + 2] = f2tf(sb0.z); Bs[0][lr][lc + 3] = f2tf(sb0.w);
        Bs[0][lr + 64][lc + 0] = f2tf(sb1.x); Bs[0][lr + 64][lc + 1] = f2tf(sb1.y);
        Bs[0][lr + 64][lc + 2] = f2tf(sb1.z); Bs[0][lr + 64][lc + 3] = f2tf(sb1.w);
    }

    const int KT = K >> 4;
    for (int kt = 0; kt < KT; kt++) {
        __syncthreads();
        const bool more = (kt + 1 < KT);
        if (more) {
            const int k0 = (kt + 1) << 4;
            sa0 = *(const float4*)(A + (size_t)(m0 + lr) * K + k0 + lc);
            sa1 = *(const float4*)(A + (size_t)(m0 + lr + 64) * K + k0 + lc);
            const int n1 = n0 + lr, n2 = n0 + lr + 64;
            sb0 = (n1 < N) ? *(const float4*)(W + (size_t)n1 * K + k0 + lc) : z4;
            sb1 = (n2 < N) ? *(const float4*)(W + (size_t)n2 * K + k0 + lc) : z4;
        }

        const int buf = kt & 1;
        #pragma unroll
        for (int ks = 0; ks < 2; ks++) {
            unsigned af[2][4], bf[8][2];
            const int c = ks * 8 + tg;
            #pragma unroll
            for (int mi = 0; mi < 2; mi++) {
                const int r = wm * 32 + mi * 16 + g;
                af[mi][0] = As[buf][r][c];
                af[mi][1] = As[buf][r + 8][c];
                af[mi][2] = As[buf][r][c + 4];
                af[mi][3] = As[buf][r + 8][c + 4];
            }
            #pragma unroll
            for (int ni = 0; ni < 8; ni++) {
                const int n = wn * 64 + ni * 8 + g;
                bf[ni][0] = Bs[buf][n][c];
                bf[ni][1] = Bs[buf][n][c + 4];
            }
            #pragma unroll
            for (int mi = 0; mi < 2; mi++)
                #pragma unroll
                for (int ni = 0; ni < 8; ni++)
                    mma_m16n8k8(acc[mi][ni], af[mi], bf[ni]);
        }

        if (more) {
            const int nb = (kt + 1) & 1;
            As[nb][lr][lc + 0] = f2tf(sa0.x); As[nb][lr][lc + 1] = f2tf(sa0.y);
            As[nb][lr][lc + 2] = f2tf(sa0.z); As[nb][lr][lc + 3] = f2tf(sa0.w);
            As[nb][lr + 64][lc + 0] = f2tf(sa1.x); As[nb][lr + 64][lc + 1] = f2tf(sa1.y);
            As[nb][lr + 64][lc + 2] = f2tf(sa1.z); As[nb][lr + 64][lc + 3] = f2tf(sa1.w);
            Bs[nb][lr][lc + 0] = f2tf(sb0.x); Bs[nb][lr][lc + 1] = f2tf(sb0.y);
            Bs[nb][lr][lc + 2] = f2tf(sb0.z); Bs[nb][lr][lc + 3] = f2tf(sb0.w);
            Bs[nb][lr + 64][lc + 0] = f2tf(sb1.x); Bs[nb][lr + 64][lc + 1] = f2tf(sb1.y);
            Bs[nb][lr + 64][lc + 2] = f2tf(sb1.z); Bs[nb][lr + 64][lc + 3] = f2tf(sb1.w);
        }
    }

    // --- epilogue ---
    #pragma unroll
    for (int mi = 0; mi < 2; mi++) {
        const int r0 = m0 + wm * 32 + mi * 16 + g;
        #pragma unroll
        for (int ni = 0; ni < 8; ni++) {
            const int c0 = n0 + wn * 64 + ni * 8 + tg * 2;
            #pragma unroll
            for (int half = 0; half < 2; half++) {
                const int m = r0 + half * 8;
                #pragma unroll
                for (int j = 0; j < 2; j++) {
                    const int n = c0 + j;
                    if (n >= N) continue;
                    float v = acc[mi][ni][half * 2 + j];
                    if (EPI == 0) {
                        C[(size_t)m * N + n] = v;
                    } else if (EPI == 1) {
                        v += bias[n];
                        v = (v > 20.0f) ? v : log1pf(expf(v));
                        C[(size_t)m * N + n] = v;
                    } else if (EPI == 2) {
                        C[(size_t)m * N + n] = v + res[(size_t)m * N + n];
                    } else { // EPI == 3
                        if (n < DTRANK) C[(size_t)m * DTRANK + n] = v;
                        else            C2[(size_t)m * 48 + (n - DTRANK)] = v;
                    }
                }
            }
        }
    }
}

// ---------------------------------------------------------------------------
// Causal depthwise conv (width 4) + bias + SiLU.
// ---------------------------------------------------------------------------
__global__ void conv_silu_kernel(const float* __restrict__ xz,
                                 const float* __restrict__ conv_w,
                                 const float* __restrict__ conv_b,
                                 float* __restrict__ u)
{
    const int idx = blockIdx.x * blockDim.x + threadIdx.x;
    if (idx >= MROWS * DINNER) return;
    const int d = idx & (DINNER - 1);
    const int m = idx >> 10;
    const int l = m & (SEQL - 1);
    const int b = m >> 10;

    const float w0 = conv_w[d * 4 + 0];
    const float w1 = conv_w[d * 4 + 1];
    const float w2 = conv_w[d * 4 + 2];
    const float w3 = conv_w[d * 4 + 3];

    float a = conv_b[d];
    const size_t base = ((size_t)(b << 10)) * E2 + d;
    if (l >= 3) a += w0 * xz[base + (size_t)(l - 3) * E2];
    if (l >= 2) a += w1 * xz[base + (size_t)(l - 2) * E2];
    if (l >= 1) a += w2 * xz[base + (size_t)(l - 1) * E2];
    a += w3 * xz[base + (size_t)l * E2];

    const float s = 1.0f / (1.0f + __expf(-a));
    u[idx] = a * s;
}

// ---------------------------------------------------------------------------
// Selective scan. 4 states/thread; lanes {4c..4c+3} = one (b,d) channel.
// ---------------------------------------------------------------------------
__global__ void scan_kernel(const float* __restrict__ bc,
                            const float* __restrict__ dt_arr,
                            const float* __restrict__ u_arr,
                            const float* __restrict__ xz,
                            const float* __restrict__ A_log,
                            const float* __restrict__ D_param,
                            float* __restrict__ y_out)
{
    const int gidx = blockIdx.x * blockDim.x + threadIdx.x;
    const int sg = gidx & 3;
    const int ch = gidx >> 2;
    const int d  = ch & (DINNER - 1);
    const int b  = ch >> 10;

    float A[4];
    #pragma unroll
    for (int i = 0; i < 4; i++)
        A[i] = -__expf(A_log[d * DSTATE + sg * 4 + i]);
    const float Dp = D_param[d];

    float h0 = 0.f, h1 = 0.f, h2 = 0.f, h3 = 0.f;
    const int rowbase = b * SEQL;

    for (int l = 0; l < SEQL; l++) {
        const int m = rowbase + l;
        const float dt = dt_arr[(size_t)m * DINNER + d];
        const float ut = u_arr[(size_t)m * DINNER + d];
        const float4 Bv = *(const float4*)(bc + (size_t)m * 48 + sg * 4);
        const float4 Cv = *(const float4*)(bc + (size_t)m * 48 + 16 + sg * 4);
        const float dtu = dt * ut;

        h0 = __expf(dt * A[0]) * h0 + dtu * Bv.x;
        h1 = __expf(dt * A[1]) * h1 + dtu * Bv.y;
        h2 = __expf(dt * A[2]) * h2 + dtu * Bv.z;
        h3 = __expf(dt * A[3]) * h3 + dtu * Bv.w;

        float acc = h0 * Cv.x + h1 * Cv.y + h2 * Cv.z + h3 * Cv.w;
        acc += __shfl_xor_sync(0xffffffffu, acc, 1);
        acc += __shfl_xor_sync(0xffffffffu, acc, 2);

        if (sg == 0) {
            const float zt = xz[(size_t)m * E2 + DINNER + d];
            const float sig = 1.0f / (1.0f + __expf(-zt));
            y_out[(size_t)m * DINNER + d] = (acc + Dp * ut) * (zt * sig);
        }
    }
}

// ---------------------------------------------------------------------------
// Launch
// ---------------------------------------------------------------------------
extern "C" void kernel_launch(void* const* d_in, const int* in_sizes, int n_in,
                              void* d_out, int out_size)
{
    const float* x         = (const float*)d_in[0];
    const float* norm_w    = (const float*)d_in[1];
    const float* norm_b    = (const float*)d_in[2];
    const float* in_proj_w = (const float*)d_in[3];
    const float* conv_w    = (const float*)d_in[4];
    const float* conv_b    = (const float*)d_in[5];
    const float* x_proj_w  = (const float*)d_in[6];
    const float* dt_proj_w = (const float*)d_in[7];
    const float* dt_proj_b = (const float*)d_in[8];
    const float* A_log     = (const float*)d_in[9];
    const float* D_param   = (const float*)d_in[10];
    const float* out_proj_w= (const float*)d_in[11];
    float* out = (float*)d_out;

    static float *p_xn = nullptr, *p_xz, *p_u, *p_dtr, *p_bc, *p_dt, *p_y;
    if (!p_xn) {
        cudaGetSymbolAddress((void**)&p_xn,  g_xn);
        cudaGetSymbolAddress((void**)&p_xz,  g_xz);
        cudaGetSymbolAddress((void**)&p_u,   g_u);
        cudaGetSymbolAddress((void**)&p_dtr, g_dtr);
        cudaGetSymbolAddress((void**)&p_bc,  g_bc);
        cudaGetSymbolAddress((void**)&p_dt,  g_dt);
        cudaGetSymbolAddress((void**)&p_y,   g_y);
    }

    // 1. LayerNorm
    layernorm_kernel<<<MROWS, 128>>>(x, norm_w, norm_b, p_xn);

    // 2. in_proj: xz[8192, 2048] = xn @ in_proj_w^T
    mma_gemm<0><<<dim3(E2 / 128, MROWS / 128), 256>>>(
        p_xn, in_proj_w, p_xz, MROWS, E2, DMODEL, nullptr, nullptr, nullptr);

    // 3. causal depthwise conv + SiLU -> u
    conv_silu_kernel<<<(MROWS * DINNER) / 256, 256>>>(p_xz, conv_w, conv_b, p_u);

    // 4. x_proj: [8192, 80] = u @ x_proj_w^T, split into dtr[.,32] and bc[.,48]
    mma_gemm<3><<<dim3(1, MROWS / 128), 256>>>(
        p_u, x_proj_w, p_dtr, MROWS, 80, DINNER, nullptr, nullptr, p_bc);

    // 5. dt_proj + bias + softplus: dt[8192, 1024]
    mma_gemm<1><<<dim3(DINNER / 128, MROWS / 128), 256>>>(
        p_dtr, dt_proj_w, p_dt, MROWS, DINNER, DTRANK, dt_proj_b, nullptr, nullptr);

    // 6. selective scan + D*u + silu(z) gate -> y
    scan_kernel<<<(MROWS * 4) / 256, 256>>>(p_bc, p_dt, p_u, p_xz, A_log, D_param, p_y);

    // 7. out_proj + residual: out[8192, 512] = y @ out_proj_w^T + x
    mma_gemm<2><<<dim3(DMODEL / 128, MROWS / 128), 256>>>(
        p_y, out_proj_w, out, MROWS, DMODEL, DINNER, nullptr, x, nullptr);
}